// round 15
// baseline (speedup 1.0000x reference)
#include <cuda_runtime.h>
#include <cuda_bf16.h>
#include <cstdint>
#include <math.h>

#define Bb 32
#define Nn 2048
#define Mm 512
#define Dd 512

#define BM 128
#define BN 128
#define BK 32
#define NT 512   // threads per gemm block (16 warps)
#define PK 40    // smem pitch in bf16 elements (conflict-free for ldmatrix)

// ---------------------------------------------------------------------------
// Scratch (static device globals — allocation-free); round-5 set, device-only refs
// ---------------------------------------------------------------------------
__device__ float g_E [(size_t)Bb*Nn*Mm];   // exp(S)   [b][n][m]
__device__ float g_Et[(size_t)Bb*Nn*Mm];   // E^T      [b][m][n]
__device__ float g_Ct[(size_t)Bb*Nn*Dd];   // C^T      [b][d][n]
__device__ float g_Qt[(size_t)Bb*Mm*Dd];   // Q^T      [b][d][m]
__device__ float g_Tt[(size_t)Bb*Mm*Dd];   // T^T      [b][d][m]
__device__ float g_rowC[Bb*Nn];
__device__ float g_rowQ[Bb*Mm];
__device__ float g_rcpRow[Bb*Nn];
__device__ float g_rcpCol[Bb*Mm];

// ---------------------------------------------------------------------------
// MMA helpers (baseline PTX)
// ---------------------------------------------------------------------------
__device__ __forceinline__ uint32_t smem_u32(const void* p){
    uint32_t a;
    asm("{ .reg .u64 t; cvta.to.shared.u64 t, %1; cvt.u32.u64 %0, t; }"
        : "=r"(a) : "l"(p));
    return a;
}
__device__ __forceinline__ void ldm_x4(uint32_t* r, const uint16_t* p){
    uint32_t a = smem_u32(p);
    asm volatile("ldmatrix.sync.aligned.m8n8.x4.shared.b16 {%0,%1,%2,%3}, [%4];"
        : "=r"(r[0]), "=r"(r[1]), "=r"(r[2]), "=r"(r[3]) : "r"(a));
}
__device__ __forceinline__ void mma_bf16(float* c, const uint32_t* a,
                                         uint32_t b0, uint32_t b1){
    asm volatile("mma.sync.aligned.m16n8k16.row.col.f32.bf16.bf16.f32 "
        "{%0,%1,%2,%3}, {%4,%5,%6,%7}, {%8,%9}, {%0,%1,%2,%3};"
        : "+f"(c[0]), "+f"(c[1]), "+f"(c[2]), "+f"(c[3])
        : "r"(a[0]), "r"(a[1]), "r"(a[2]), "r"(a[3]), "r"(b0), "r"(b1));
}

// ---------------------------------------------------------------------------
// Register fragments (512-thread tiling: 64 rows x 32 k per sweep)
// ---------------------------------------------------------------------------
template<int ROWS>
struct TileFrag { float4 v[ROWS/64]; };

template<int ROWS>
__device__ __forceinline__ void frag_load(TileFrag<ROWS>& f,
    const float* __restrict__ src, int pitch, int r0, int k0, int tid)
{
    int rr = tid >> 3;            // 0..63
    int c4 = (tid & 7) * 4;       // 0,4,...,28
#pragma unroll
    for (int it = 0; it < ROWS/64; it++)
        f.v[it] = *reinterpret_cast<const float4*>(
            src + (size_t)(r0 + rr + it*64)*pitch + k0 + c4);
}

template<int ROWS>
__device__ __forceinline__ void frag_stage(const TileFrag<ROWS>& f,
    uint16_t* __restrict__ hi, uint16_t* __restrict__ lo,
    const float* __restrict__ wvec, const int* __restrict__ kmask,
    int k0, int tid)
{
    int rr = tid >> 3;
    int c4 = (tid & 7) * 4;
    float4 wv = make_float4(1.f, 1.f, 1.f, 1.f);
    if (wvec) wv = *reinterpret_cast<const float4*>(wvec + k0 + c4);
    int4 mk = make_int4(0, 0, 0, 0);
    if (kmask) mk = *reinterpret_cast<const int4*>(kmask + k0 + c4);
#pragma unroll
    for (int it = 0; it < ROWS/64; it++){
        int r = rr + it*64;
        float4 v = f.v[it];
        v.x *= wv.x; v.y *= wv.y; v.z *= wv.z; v.w *= wv.w;
        if (kmask){
            v.x = mk.x ? 0.f : v.x;  v.y = mk.y ? 0.f : v.y;
            v.z = mk.z ? 0.f : v.z;  v.w = mk.w ? 0.f : v.w;
        }
        __nv_bfloat16 hx = __float2bfloat16_rn(v.x);
        __nv_bfloat16 hy = __float2bfloat16_rn(v.y);
        __nv_bfloat16 hz = __float2bfloat16_rn(v.z);
        __nv_bfloat16 hw = __float2bfloat16_rn(v.w);
        __nv_bfloat16 lx = __float2bfloat16_rn(v.x - __bfloat162float(hx));
        __nv_bfloat16 ly = __float2bfloat16_rn(v.y - __bfloat162float(hy));
        __nv_bfloat16 lz = __float2bfloat16_rn(v.z - __bfloat162float(hz));
        __nv_bfloat16 lw = __float2bfloat16_rn(v.w - __bfloat162float(hw));
        uint32_t off = r*PK + c4;
        *reinterpret_cast<__nv_bfloat162*>(hi + off)     = __halves2bfloat162(hx, hy);
        *reinterpret_cast<__nv_bfloat162*>(hi + off + 2) = __halves2bfloat162(hz, hw);
        *reinterpret_cast<__nv_bfloat162*>(lo + off)     = __halves2bfloat162(lx, ly);
        *reinterpret_cast<__nv_bfloat162*>(lo + off + 2) = __halves2bfloat162(lz, lw);
    }
}

// ---------------------------------------------------------------------------
// Warp MMA on one staged BK=32 chunk; warp tile 32x32; bf16x3 (hh+hl+lh)
// wm, wn in 0..3 (16 warps, 128x128 block tile)
// ---------------------------------------------------------------------------
__device__ __forceinline__ void warp_mma_tile(
    float acc[2][4][4],
    const uint16_t* __restrict__ Ahi, const uint16_t* __restrict__ Alo,
    const uint16_t* __restrict__ Bhi, const uint16_t* __restrict__ Blo,
    int wm, int wn, int lane)
{
    int rsel = lane & 15;
    int ksel = (lane >> 4) * 8;
#pragma unroll
    for (int ks = 0; ks < 2; ks++){
        uint32_t ah[2][4], al[2][4];
#pragma unroll
        for (int mt = 0; mt < 2; mt++){
            ldm_x4(ah[mt], Ahi + (wm*32 + mt*16 + rsel)*PK + ks*16 + ksel);
            ldm_x4(al[mt], Alo + (wm*32 + mt*16 + rsel)*PK + ks*16 + ksel);
        }
        uint32_t bh[2][4], bl[2][4];
#pragma unroll
        for (int g = 0; g < 2; g++){
            ldm_x4(bh[g], Bhi + (wn*32 + g*16 + rsel)*PK + ks*16 + ksel);
            ldm_x4(bl[g], Blo + (wn*32 + g*16 + rsel)*PK + ks*16 + ksel);
        }
#pragma unroll
        for (int mt = 0; mt < 2; mt++)
#pragma unroll
        for (int nt = 0; nt < 4; nt++){
            uint32_t b0h = bh[nt>>1][nt & 1], b1h = bh[nt>>1][(nt & 1) + 2];
            uint32_t b0l = bl[nt>>1][nt & 1], b1l = bl[nt>>1][(nt & 1) + 2];
            mma_bf16(acc[mt][nt], ah[mt], b0h, b1h);
            mma_bf16(acc[mt][nt], ah[mt], b0l, b1l);
            mma_bf16(acc[mt][nt], al[mt], b0h, b1h);
        }
    }
}

// ---------------------------------------------------------------------------
// gemmS: E[b,n,m] = exp( rowC[n] + rowQ[m] + sum_d (C*w3)[n,d]*Q[m,d] )
// ---------------------------------------------------------------------------
__global__ void __launch_bounds__(NT) gemmS_mma(
    const float* __restrict__ C, const float* __restrict__ Q,
    const float* __restrict__ w)
{
    __shared__ uint16_t Ah[BM*PK], Al[BM*PK], Bh[BN*PK], Bl[BN*PK];
    int tid = threadIdx.x, lane = tid & 31, wid = tid >> 5;
    int wm = wid >> 2, wn = wid & 3;
    int b = blockIdx.z, n0 = blockIdx.y*BM, m0 = blockIdx.x*BN;
    const float* Cb = C + (size_t)b*Nn*Dd;
    const float* Qb = Q + (size_t)b*Mm*Dd;
    const float* w3 = w + 2*Dd;

    TileFrag<BM> fa; TileFrag<BN> fb;
    frag_load(fa, Cb, Dd, n0, 0, tid);
    frag_load(fb, Qb, Dd, m0, 0, tid);

    float acc[2][4][4] = {};
    for (int k0 = 0; k0 < Dd; k0 += BK){
        __syncthreads();
        frag_stage(fa, Ah, Al, w3, nullptr, k0, tid);
        frag_stage(fb, Bh, Bl, nullptr, nullptr, k0, tid);
        __syncthreads();
        if (k0 + BK < Dd){
            frag_load(fa, Cb, Dd, n0, k0 + BK, tid);
            frag_load(fb, Qb, Dd, m0, k0 + BK, tid);
        }
        warp_mma_tile(acc, Ah, Al, Bh, Bl, wm, wn, lane);
    }

    int rg = lane >> 2, cg = (lane & 3)*2;
#pragma unroll
    for (int mt = 0; mt < 2; mt++)
#pragma unroll
    for (int nt = 0; nt < 4; nt++)
#pragma unroll
    for (int h = 0; h < 2; h++){
        int n = n0 + wm*32 + mt*16 + rg + h*8;
        int m = m0 + wn*32 + nt*8 + cg;
        float rc = g_rowC[b*Nn + n];
        float2 o;
        o.x = __expf(acc[mt][nt][h*2+0] + rc + g_rowQ[b*Mm + m + 0]);
        o.y = __expf(acc[mt][nt][h*2+1] + rc + g_rowQ[b*Mm + m + 1]);
        *reinterpret_cast<float2*>(&g_E[(size_t)(b*Nn + n)*Mm + m]) = o;
    }
}

// ---------------------------------------------------------------------------
// gemmT: Tt[b,d,m] = rcpCol[m] * sum_n Ct[d,n] * (Cmask[n]? 0 : Et[m,n])
// ---------------------------------------------------------------------------
__global__ void __launch_bounds__(NT) gemmT_mma(const int* __restrict__ Cmask)
{
    __shared__ uint16_t Ah[BM*PK], Al[BM*PK], Bh[BN*PK], Bl[BN*PK];
    int tid = threadIdx.x, lane = tid & 31, wid = tid >> 5;
    int wm = wid >> 2, wn = wid & 3;
    int b = blockIdx.z, d0 = blockIdx.y*BM, m0 = blockIdx.x*BN;
    const float* Ab = g_Ct + (size_t)b*Dd*Nn;   // [d][n]
    const float* Bp = g_Et + (size_t)b*Mm*Nn;   // [m][n]
    const int*   cm = Cmask + b*Nn;

    TileFrag<BM> fa; TileFrag<BN> fb;
    frag_load(fa, Ab, Nn, d0, 0, tid);
    frag_load(fb, Bp, Nn, m0, 0, tid);

    float acc[2][4][4] = {};
    for (int k0 = 0; k0 < Nn; k0 += BK){
        __syncthreads();
        frag_stage(fa, Ah, Al, nullptr, nullptr, k0, tid);
        frag_stage(fb, Bh, Bl, nullptr, cm, k0, tid);
        __syncthreads();
        if (k0 + BK < Nn){
            frag_load(fa, Ab, Nn, d0, k0 + BK, tid);
            frag_load(fb, Bp, Nn, m0, k0 + BK, tid);
        }
        warp_mma_tile(acc, Ah, Al, Bh, Bl, wm, wn, lane);
    }

    int rg = lane >> 2, cg = (lane & 3)*2;
#pragma unroll
    for (int mt = 0; mt < 2; mt++)
#pragma unroll
    for (int nt = 0; nt < 4; nt++)
#pragma unroll
    for (int h = 0; h < 2; h++){
        int d = d0 + wm*32 + mt*16 + rg + h*8;
        int m = m0 + wn*32 + nt*8 + cg;
        float2 o;
        o.x = acc[mt][nt][h*2+0] * g_rcpCol[b*Mm + m + 0];
        o.y = acc[mt][nt][h*2+1] * g_rcpCol[b*Mm + m + 1];
        *reinterpret_cast<float2*>(&g_Tt[((size_t)b*Dd + d)*Mm + m]) = o;
    }
}

// ---------------------------------------------------------------------------
// gemmAB: A   [b,n,d] = rcpRow[n] * sum_m E[n,m] * (Qmask[m]? 0 : Qt[d,m])
//         Bout[b,n,d] = rcpRow[n] * sum_m E[n,m] * (Qmask[m]? 0 : Tt[d,m])
// Dynamic smem: Ah 0, Al 5120, B1h 10240, B1l 15360, B2h 20480, B2l 25600 (elems)
// ---------------------------------------------------------------------------
__global__ void __launch_bounds__(NT) gemmAB_mma(
    const int* __restrict__ Qmask, float* __restrict__ outA,
    float* __restrict__ outB)
{
    extern __shared__ uint16_t sm[];
    uint16_t *Ah = sm, *Al = sm + 5120;
    uint16_t *B1h = sm + 10240, *B1l = sm + 15360;
    uint16_t *B2h = sm + 20480, *B2l = sm + 25600;
    int tid = threadIdx.x, lane = tid & 31, wid = tid >> 5;
    int wm = wid >> 2, wn = wid & 3;
    int b = blockIdx.z, n0 = blockIdx.y*BM, d0 = blockIdx.x*BN;
    const float* Eb  = g_E  + (size_t)b*Nn*Mm;   // [n][m]
    const float* Qtb = g_Qt + (size_t)b*Dd*Mm;   // [d][m]
    const float* Ttb = g_Tt + (size_t)b*Dd*Mm;   // [d][m]
    const int*   qm  = Qmask + b*Mm;

    TileFrag<BM> fa; TileFrag<BN> fb1, fb2;
    frag_load(fa,  Eb,  Mm, n0, 0, tid);
    frag_load(fb1, Qtb, Mm, d0, 0, tid);
    frag_load(fb2, Ttb, Mm, d0, 0, tid);

    float accA[2][4][4] = {};
    float accB[2][4][4] = {};
    for (int k0 = 0; k0 < Mm; k0 += BK){
        __syncthreads();
        frag_stage(fa,  Ah,  Al,  nullptr, nullptr, k0, tid);
        frag_stage(fb1, B1h, B1l, nullptr, qm, k0, tid);
        frag_stage(fb2, B2h, B2l, nullptr, qm, k0, tid);
        __syncthreads();
        if (k0 + BK < Mm){
            frag_load(fa,  Eb,  Mm, n0, k0 + BK, tid);
            frag_load(fb1, Qtb, Mm, d0, k0 + BK, tid);
            frag_load(fb2, Ttb, Mm, d0, k0 + BK, tid);
        }
        warp_mma_tile(accA, Ah, Al, B1h, B1l, wm, wn, lane);
        warp_mma_tile(accB, Ah, Al, B2h, B2l, wm, wn, lane);
    }

    int rg = lane >> 2, cg = (lane & 3)*2;
#pragma unroll
    for (int mt = 0; mt < 2; mt++)
#pragma unroll
    for (int nt = 0; nt < 4; nt++)
#pragma unroll
    for (int h = 0; h < 2; h++){
        int n = n0 + wm*32 + mt*16 + rg + h*8;
        int d = d0 + wn*32 + nt*8 + cg;
        float rr = g_rcpRow[b*Nn + n];
        size_t idx = (size_t)(b*Nn + n)*Dd + d;
        float2 oa = { accA[mt][nt][h*2+0]*rr, accA[mt][nt][h*2+1]*rr };
        float2 ob = { accB[mt][nt][h*2+0]*rr, accB[mt][nt][h*2+1]*rr };
        *reinterpret_cast<float2*>(&outA[idx]) = oa;
        *reinterpret_cast<float2*>(&outB[idx]) = ob;
    }
}

// ---------------------------------------------------------------------------
// Row-dot kernels (round-5 verbatim)
// ---------------------------------------------------------------------------
__global__ void rowdotC_kernel(const float* __restrict__ C, const float* __restrict__ w)
{
    int warp = (blockIdx.x * blockDim.x + threadIdx.x) >> 5;
    int lane = threadIdx.x & 31;
    if (warp >= Bb * Nn) return;
    const float4* x4 = reinterpret_cast<const float4*>(C + (size_t)warp * Dd);
    const float4* w4 = reinterpret_cast<const float4*>(w);
    float s = 0.f;
#pragma unroll
    for (int j = 0; j < 4; j++){
        float4 a = x4[lane + j*32]; float4 b = w4[lane + j*32];
        s += a.x*b.x + a.y*b.y + a.z*b.z + a.w*b.w;
    }
#pragma unroll
    for (int o = 16; o; o >>= 1) s += __shfl_xor_sync(~0u, s, o);
    if (lane == 0) g_rowC[warp] = s;
}

__global__ void rowdotQ_kernel(const float* __restrict__ Q, const float* __restrict__ w)
{
    int warp = (blockIdx.x * blockDim.x + threadIdx.x) >> 5;
    int lane = threadIdx.x & 31;
    if (warp >= Bb * Mm) return;
    const float4* x4 = reinterpret_cast<const float4*>(Q + (size_t)warp * Dd);
    const float4* w4 = reinterpret_cast<const float4*>(w + Dd);
    float s = 0.f;
#pragma unroll
    for (int j = 0; j < 4; j++){
        float4 a = x4[lane + j*32]; float4 b = w4[lane + j*32];
        s += a.x*b.x + a.y*b.y + a.z*b.z + a.w*b.w;
    }
#pragma unroll
    for (int o = 16; o; o >>= 1) s += __shfl_xor_sync(~0u, s, o);
    if (lane == 0) g_rowQ[warp] = s;
}

// ---------------------------------------------------------------------------
// Transpose kernels (round-5 verbatim)
// ---------------------------------------------------------------------------
__device__ __forceinline__ void transpose_body(
    const float* __restrict__ src, float* __restrict__ dst, int rows, int cols)
{
    __shared__ float t[32][33];
    int b = blockIdx.z;
    const float* s = src + (size_t)b*rows*cols;
    float* d = dst + (size_t)b*rows*cols;
    int c0 = blockIdx.x*32, r0 = blockIdx.y*32;
    int tx = threadIdx.x & 31, ty = threadIdx.x >> 5;
#pragma unroll
    for (int j = 0; j < 4; j++)
        t[ty + 8*j][tx] = s[(size_t)(r0 + ty + 8*j)*cols + c0 + tx];
    __syncthreads();
#pragma unroll
    for (int j = 0; j < 4; j++)
        d[(size_t)(c0 + ty + 8*j)*rows + r0 + tx] = t[tx][ty + 8*j];
}
__global__ void __launch_bounds__(256) transposeC_kernel(const float* __restrict__ C)
{ transpose_body(C, g_Ct, Nn, Dd); }
__global__ void __launch_bounds__(256) transposeQ_kernel(const float* __restrict__ Q)
{ transpose_body(Q, g_Qt, Mm, Dd); }
__global__ void __launch_bounds__(256) transposeE_kernel()
{ transpose_body(g_E, g_Et, Nn, Mm); }

// ---------------------------------------------------------------------------
// Masked reductions -> reciprocals (round-5 verbatim)
// ---------------------------------------------------------------------------
__global__ void rowsum_kernel(const int* __restrict__ Qmask)
{
    int warp = (blockIdx.x * blockDim.x + threadIdx.x) >> 5;
    int lane = threadIdx.x & 31;
    if (warp >= Bb * Nn) return;
    int b = warp / Nn;
    const float4* e4 = reinterpret_cast<const float4*>(g_E + (size_t)warp * Mm);
    const int4*   q4 = reinterpret_cast<const int4*>(Qmask + b * Mm);
    float s = 0.f;
#pragma unroll
    for (int j = 0; j < 4; j++){
        float4 v = e4[lane + j*32];
        int4   q = q4[lane + j*32];
        s += (q.x ? 0.f : v.x) + (q.y ? 0.f : v.y) + (q.z ? 0.f : v.z) + (q.w ? 0.f : v.w);
    }
#pragma unroll
    for (int o = 16; o; o >>= 1) s += __shfl_xor_sync(~0u, s, o);
    if (lane == 0) g_rcpRow[warp] = 1.f / s;
}

__global__ void colsumT_kernel(const int* __restrict__ Cmask)
{
    int warp = (blockIdx.x * blockDim.x + threadIdx.x) >> 5;
    int lane = threadIdx.x & 31;
    if (warp >= Bb * Mm) return;
    int b = warp / Mm;
    const float4* e4 = reinterpret_cast<const float4*>(g_Et + (size_t)warp * Nn);
    const int4*   c4 = reinterpret_cast<const int4*>(Cmask + b * Nn);
    float s = 0.f;
#pragma unroll
    for (int j = 0; j < 16; j++){
        float4 v = e4[lane + j*32];
        int4   c = c4[lane + j*32];
        s += (c.x ? 0.f : v.x) + (c.y ? 0.f : v.y) + (c.z ? 0.f : v.z) + (c.w ? 0.f : v.w);
    }
#pragma unroll
    for (int o = 16; o; o >>= 1) s += __shfl_xor_sync(~0u, s, o);
    if (lane == 0) g_rcpCol[warp] = 1.f / s;
}

// ---------------------------------------------------------------------------
extern "C" void kernel_launch(void* const* d_in, const int* in_sizes, int n_in,
                              void* d_out, int out_size)
{
    const float* C     = (const float*)d_in[0];
    const float* Q     = (const float*)d_in[1];
    const int*   Cmask = (const int*)d_in[2];
    const int*   Qmask = (const int*)d_in[3];
    const float* w     = (const float*)d_in[4];

    float* outA = (float*)d_out;
    float* outB = outA + (size_t)Bb * Nn * Dd;

    const int SMEM_AB = 6 * BM * PK * 2;   // 61440 B
    cudaFuncSetAttribute(gemmAB_mma, cudaFuncAttributeMaxDynamicSharedMemorySize, SMEM_AB);

    // 1. row dots + input transposes
    rowdotC_kernel<<<(Bb*Nn)/8, 256>>>(C, w);
    rowdotQ_kernel<<<(Bb*Mm)/8, 256>>>(Q, w);
    transposeC_kernel<<<dim3(Dd/32, Nn/32, Bb), 256>>>(C);
    transposeQ_kernel<<<dim3(Dd/32, Mm/32, Bb), 256>>>(Q);

    // 2. E = exp(S)   (tensor core, bf16x3, 128x128 tiles)
    gemmS_mma<<<dim3(Mm/BN, Nn/BM, Bb), NT>>>(C, Q, w);

    // 3. E^T + masked reductions
    transposeE_kernel<<<dim3(Mm/32, Nn/32, Bb), 256>>>();
    rowsum_kernel<<<(Bb*Nn)/8, 256>>>(Qmask);
    colsumT_kernel<<<(Bb*Mm)/8, 256>>>(Cmask);

    // 4. T^T (tensor core)
    gemmT_mma<<<dim3(Mm/BN, Dd/BM, Bb), NT>>>(Cmask);

    // 5. A and Bout (tensor core, fused)
    gemmAB_mma<<<dim3(Dd/BN, Nn/BM, Bb), NT, SMEM_AB>>>(Qmask, outA, outB);
}